// round 2
// baseline (speedup 1.0000x reference)
#include <cuda_runtime.h>
#include <cstdint>
#include <cstddef>

typedef unsigned long long u64;

#define B_  8
#define N_  1024
#define C_  768
#define H_  12
#define D_  64
#define C3  2304
#define M_  8192   // B_*N_

// ---------------- scratch (device globals; no runtime allocation) ----------
__device__ float g_qkv [(size_t)M_ * C3];   // [8192, 2304]
__device__ float g_attn[(size_t)M_ * C_];   // [8192, 768]  attention out in [B,N,C]
__device__ u64   g_sbits[3 * B_ * H_ * N_]; // [which][b][h][n] packed spikes (64 bits = D)
__device__ float g_psum[32 * C3];
__device__ float g_psq [32 * C3];
__device__ float g_scale[C3];
__device__ float g_shift[C3];

// ---------------- fp32 SGEMM: C[M,N] = A[M,K] * B[N,K]^T (+bias) -----------
// 128x128 block tile, BK=16, 8x8 per-thread micro-tile, 256 threads.
template <bool BIAS>
__global__ __launch_bounds__(256)
void sgemm_nt(const float* __restrict__ A, const float* __restrict__ Bm,
              const float* __restrict__ bias, float* __restrict__ Cm,
              int M, int N, int K)
{
    __shared__ float As[16][128];
    __shared__ float Bs[16][128];

    const int tid = threadIdx.x;
    const int tx = tid & 15, ty = tid >> 4;
    const int bm = blockIdx.y, bn = blockIdx.x;

    const float* Ab = A  + (size_t)bm * 128 * K;
    const float* Bb = Bm + (size_t)bn * 128 * K;

    float acc[8][8];
#pragma unroll
    for (int i = 0; i < 8; ++i)
#pragma unroll
        for (int j = 0; j < 8; ++j) acc[i][j] = 0.f;

    const int lrow = tid >> 2;        // 0..63
    const int lk   = (tid & 3) << 2;  // 0,4,8,12

    for (int k0 = 0; k0 < K; k0 += 16) {
#pragma unroll
        for (int hh = 0; hh < 2; ++hh) {
            int r = lrow + hh * 64;
            float4 va = *(const float4*)(Ab + (size_t)r * K + k0 + lk);
            As[lk + 0][r] = va.x; As[lk + 1][r] = va.y;
            As[lk + 2][r] = va.z; As[lk + 3][r] = va.w;
            float4 vb = *(const float4*)(Bb + (size_t)r * K + k0 + lk);
            Bs[lk + 0][r] = vb.x; Bs[lk + 1][r] = vb.y;
            Bs[lk + 2][r] = vb.z; Bs[lk + 3][r] = vb.w;
        }
        __syncthreads();
#pragma unroll
        for (int kk = 0; kk < 16; ++kk) {
            float a[8], b[8];
            *(float4*)(a)     = *(const float4*)&As[kk][ty * 8];
            *(float4*)(a + 4) = *(const float4*)&As[kk][ty * 8 + 4];
            *(float4*)(b)     = *(const float4*)&Bs[kk][tx * 8];
            *(float4*)(b + 4) = *(const float4*)&Bs[kk][tx * 8 + 4];
#pragma unroll
            for (int i = 0; i < 8; ++i)
#pragma unroll
                for (int j = 0; j < 8; ++j)
                    acc[i][j] = fmaf(a[i], b[j], acc[i][j]);
        }
        __syncthreads();
    }

#pragma unroll
    for (int i = 0; i < 8; ++i) {
        size_t row = (size_t)bm * 128 + ty * 8 + i;
#pragma unroll
        for (int j = 0; j < 8; j += 4) {
            int col = bn * 128 + tx * 8 + j;
            float4 v;
            v.x = acc[i][j + 0]; v.y = acc[i][j + 1];
            v.z = acc[i][j + 2]; v.w = acc[i][j + 3];
            if (BIAS) {
                v.x += bias[col + 0]; v.y += bias[col + 1];
                v.z += bias[col + 2]; v.w += bias[col + 3];
            }
            *(float4*)(Cm + row * N + col) = v;
        }
    }
}

// ---------------- BN stats: deterministic two-stage column reduction -------
__global__ __launch_bounds__(256)
void bn_stats(const float* __restrict__ qkv)
{
    int c  = blockIdx.x * 256 + threadIdx.x;   // 0..2303
    int r0 = blockIdx.y * 256;
    float s = 0.f, q = 0.f;
    for (int i = 0; i < 256; ++i) {
        float v = qkv[(size_t)(r0 + i) * C3 + c];
        s += v; q += v * v;
    }
    g_psum[blockIdx.y * C3 + c] = s;
    g_psq [blockIdx.y * C3 + c] = q;
}

__global__ __launch_bounds__(256)
void bn_finalize(const float* __restrict__ gamma, const float* __restrict__ beta)
{
    int c = blockIdx.x * 256 + threadIdx.x;
    float s = 0.f, q = 0.f;
    for (int i = 0; i < 32; ++i) { s += g_psum[i * C3 + c]; q += g_psq[i * C3 + c]; }
    float mean = s * (1.f / M_);
    float var  = q * (1.f / M_) - mean * mean;   // biased, as torch BN / jnp.var
    float rs   = rsqrtf(var + 1e-5f);
    float sc   = gamma[c] * rs;
    g_scale[c] = sc;
    g_shift[c] = beta[c] - mean * sc;
}

// ---------------- fused BN-apply + multistep LIF + bit-pack ----------------
// thread = (which, h, n); handles all 64 lanes d, sequential over time b=0..7.
// LIF: v = (v + x)/2; spike = v>=1; hard reset v=0 on spike.
__global__ __launch_bounds__(256)
void bnlif(const float* __restrict__ qkv)
{
    int gid   = blockIdx.x * 256 + threadIdx.x;  // 0..36863
    int n     = gid & 1023;
    int t     = gid >> 10;                       // 0..35
    int h     = t % H_;
    int which = t / H_;
    int c0    = which * C_ + h * D_;

    u64 bits[B_];
#pragma unroll
    for (int b = 0; b < B_; ++b) bits[b] = 0ull;

#pragma unroll
    for (int dq = 0; dq < 4; ++dq) {             // 4 chunks of 16 lanes
        int cb = c0 + dq * 16;
        float sc[16], sh[16];
#pragma unroll
        for (int q4 = 0; q4 < 4; ++q4) {
            *(float4*)(sc + q4 * 4) = *(const float4*)(g_scale + cb + q4 * 4);
            *(float4*)(sh + q4 * 4) = *(const float4*)(g_shift + cb + q4 * 4);
        }
        float v[16];
#pragma unroll
        for (int d = 0; d < 16; ++d) v[d] = 0.f;

#pragma unroll
        for (int b = 0; b < B_; ++b) {
            const float* row = qkv + (size_t)(b * N_ + n) * C3 + cb;
            float xv[16];
#pragma unroll
            for (int q4 = 0; q4 < 4; ++q4)
                *(float4*)(xv + q4 * 4) = *(const float4*)(row + q4 * 4);
#pragma unroll
            for (int d = 0; d < 16; ++d) {
                float y = fmaf(xv[d], sc[d], sh[d]);
                v[d] = 0.5f * (v[d] + y);
                if (v[d] >= 1.0f) {
                    bits[b] |= 1ull << (dq * 16 + d);
                    v[d] = 0.f;
                }
            }
        }
    }
#pragma unroll
    for (int b = 0; b < B_; ++b)
        g_sbits[((size_t)(which * B_ + b) * H_ + h) * N_ + n] = bits[b];
}

// ---------------- attention: popcount QK + table-exp + fp32 PV GEMM --------
// grid (96 = B*H, 8 row-tiles of 128), 256 threads.
// One pass softmax: acc = sum_j exp(s_ij/8)*v_j ; normalize by sum_j exp at end.
#define OFF_ET   0
#define OFF_VS   (OFF_ET + 128 * 128 * 4)        // 65536
#define OFF_SKB  (OFF_VS + 128 * 64 * 4)         // 98304
#define OFF_SVB  (OFF_SKB + 1024 * 8)            // 106496
#define OFF_SQB  (OFF_SVB + 1024 * 8)            // 114688
#define OFF_TAB  (OFF_SQB + 128 * 8)             // 115712
#define OFF_DEN  (OFF_TAB + 272)                 // 115984
#define ATTN_SMEM (OFF_DEN + 256 * 4)            // 117008

__global__ __launch_bounds__(256)
void attn_kernel(float* __restrict__ out)
{
    extern __shared__ char smem[];
    float* Et   = (float*)(smem + OFF_ET);    // [128j][128r]
    float* Vs   = (float*)(smem + OFF_VS);    // [128j][64d]
    u64*   skb  = (u64*)  (smem + OFF_SKB);   // 1024
    u64*   svb  = (u64*)  (smem + OFF_SVB);   // 1024
    u64*   sqb  = (u64*)  (smem + OFF_SQB);   // 128
    float* tab  = (float*)(smem + OFF_TAB);   // 65 (padded)
    float* den2 = (float*)(smem + OFF_DEN);   // 256

    const int tid = threadIdx.x;
    const int bh  = blockIdx.x;   // 0..95
    const int rt  = blockIdx.y;   // 0..7
    const int b   = bh / H_, h = bh % H_;

    const u64* qb = g_sbits + ((size_t)(0 * B_ + b) * H_ + h) * N_;
    const u64* kb = g_sbits + ((size_t)(1 * B_ + b) * H_ + h) * N_;
    const u64* vb = g_sbits + ((size_t)(2 * B_ + b) * H_ + h) * N_;

    for (int i = tid; i < N_; i += 256) { skb[i] = kb[i]; svb[i] = vb[i]; }
    if (tid < 128) sqb[tid] = qb[rt * 128 + tid];
    if (tid < 65)  tab[tid] = expf(0.125f * (float)tid);   // SCALE = 1/sqrt(64)
    __syncthreads();

    const int r = tid >> 1, half = tid & 1;
    const u64 qr = sqb[r];
    const int ty = tid >> 4, tx = tid & 15;

    float acc[8][4];
#pragma unroll
    for (int i = 0; i < 8; ++i)
#pragma unroll
        for (int k = 0; k < 4; ++k) acc[i][k] = 0.f;
    float den_local = 0.f;

    for (int jt = 0; jt < 8; ++jt) {
        // phase A: exp table lookups -> Et (transposed), plus denominator
        const u64* kt = skb + jt * 128 + half * 64;
#pragma unroll 4
        for (int jj = 0; jj < 64; ++jj) {
            int s = __popcll(qr & kt[jj]);
            float e = tab[s];
            Et[(half * 64 + jj) * 128 + r] = e;
            den_local += e;
        }
        // unpack v bits -> fp32 tile
        for (int idx = tid; idx < 128 * 64; idx += 256) {
            int j = idx >> 6, d = idx & 63;
            Vs[idx] = (float)((svb[jt * 128 + j] >> d) & 1ull);
        }
        __syncthreads();
        // phase B: out[128x64] += Et^T[128r x 128j] * Vs[128j x 64d]
#pragma unroll 2
        for (int j = 0; j < 128; ++j) {
            float a[8], bb[4];
            *(float4*)(a)     = *(const float4*)&Et[j * 128 + ty * 8];
            *(float4*)(a + 4) = *(const float4*)&Et[j * 128 + ty * 8 + 4];
            *(float4*)(bb)    = *(const float4*)&Vs[j * 64 + tx * 4];
#pragma unroll
            for (int i = 0; i < 8; ++i)
#pragma unroll
                for (int k = 0; k < 4; ++k)
                    acc[i][k] = fmaf(a[i], bb[k], acc[i][k]);
        }
        __syncthreads();
    }

    den2[tid] = den_local;   // tid = r*2 + half
    __syncthreads();

#pragma unroll
    for (int i = 0; i < 8; ++i) {
        int row = ty * 8 + i;
        float inv = 1.f / (den2[row * 2] + den2[row * 2 + 1]);
        size_t o = ((size_t)(b * N_) + rt * 128 + row) * C_ + h * D_ + tx * 4;
        float4 v;
        v.x = acc[i][0] * inv; v.y = acc[i][1] * inv;
        v.z = acc[i][2] * inv; v.w = acc[i][3] * inv;
        *(float4*)(out + o) = v;
    }
}

// ---------------- launch ----------------------------------------------------
extern "C" void kernel_launch(void* const* d_in, const int* in_sizes, int n_in,
                              void* d_out, int out_size)
{
    const float* x      = (const float*)d_in[0];
    const float* w_qkv  = (const float*)d_in[1];
    const float* gamma  = (const float*)d_in[2];
    const float* beta   = (const float*)d_in[3];
    const float* w_proj = (const float*)d_in[4];
    const float* b_proj = (const float*)d_in[5];
    float* out = (float*)d_out;

    float* qkv  = nullptr;
    float* attn = nullptr;
    cudaGetSymbolAddress((void**)&qkv,  g_qkv);
    cudaGetSymbolAddress((void**)&attn, g_attn);

    cudaFuncSetAttribute(attn_kernel,
                         cudaFuncAttributeMaxDynamicSharedMemorySize, ATTN_SMEM);

    // 1) qkv = x @ w_qkv^T   [8192,2304]
    sgemm_nt<false><<<dim3(C3 / 128, M_ / 128), 256>>>(x, w_qkv, nullptr, qkv, M_, C3, C_);
    // 2) BN stats (deterministic 2-stage)
    bn_stats<<<dim3(9, 32), 256>>>(qkv);
    bn_finalize<<<9, 256>>>(gamma, beta);
    // 3) BN apply + LIF + spike bit-pack
    bnlif<<<144, 256>>>(qkv);
    // 4) spiking attention (popcount QK, table softmax, fp32 PV)
    attn_kernel<<<dim3(B_ * H_, 8), 256, ATTN_SMEM>>>(attn);
    // 5) proj = attn @ w_proj^T + b_proj
    sgemm_nt<true><<<dim3(C_ / 128, M_ / 128), 256>>>(attn, w_proj, b_proj, out, M_, C_, C_);
}

// round 5
// speedup vs baseline: 1.5712x; 1.5712x over previous
#include <cuda_runtime.h>
#include <cuda_bf16.h>
#include <cstdint>
#include <cstddef>

typedef unsigned long long u64;
typedef unsigned int u32;

#define B_  8
#define N_  1024
#define C_  768
#define H_  12
#define D_  64
#define C3  2304
#define M_  8192   // B_*N_

// ---------------- scratch (device globals; no runtime allocation) ----------
__device__ float g_qkv [(size_t)M_ * C3];   // [8192, 2304] fp32
__device__ u64   g_sbits[3 * B_ * H_ * N_]; // [which][b][h][n] packed spikes
__device__ float g_psum[32 * C3];
__device__ float g_psq [32 * C3];
__device__ float g_scale[C3];
__device__ float g_shift[C3];
// bf16 split operands
__device__ __nv_bfloat16 g_xhi [(size_t)M_ * C_];
__device__ __nv_bfloat16 g_xlo [(size_t)M_ * C_];
__device__ __nv_bfloat16 g_w1hi[(size_t)C3 * C_];
__device__ __nv_bfloat16 g_w1lo[(size_t)C3 * C_];
__device__ __nv_bfloat16 g_ahi [(size_t)M_ * C_];   // attention out split
__device__ __nv_bfloat16 g_alo [(size_t)M_ * C_];
__device__ __nv_bfloat16 g_w2hi[(size_t)C_ * C_];
__device__ __nv_bfloat16 g_w2lo[(size_t)C_ * C_];

// ======================= baseline-PTX helpers ===============================
__device__ __forceinline__ u32 smem_to_u32(const void* p) {
    u32 a;
    asm("{ .reg .u64 t; cvta.to.shared.u64 t, %1; cvt.u32.u64 %0, t; }"
        : "=r"(a) : "l"(p));
    return a;
}
__device__ __forceinline__ void cp16(u32 dst, const void* src) {
    asm volatile("cp.async.cg.shared.global [%0], [%1], 16;"
                 :: "r"(dst), "l"(src));
}
#define CP_COMMIT() asm volatile("cp.async.commit_group;" ::: "memory")
template <int NN> __device__ __forceinline__ void cp_wait() {
    asm volatile("cp.async.wait_group %0;" :: "n"(NN) : "memory");
}
__device__ __forceinline__ void ldsm4(u32* r, u32 addr) {
    asm volatile("ldmatrix.sync.aligned.m8n8.x4.shared.b16 {%0,%1,%2,%3}, [%4];"
                 : "=r"(r[0]), "=r"(r[1]), "=r"(r[2]), "=r"(r[3]) : "r"(addr));
}
__device__ __forceinline__ void mma_bf16(float* c, const u32* a, const u32* b) {
    asm volatile(
        "mma.sync.aligned.m16n8k16.row.col.f32.bf16.bf16.f32 "
        "{%0,%1,%2,%3}, {%4,%5,%6,%7}, {%8,%9}, {%0,%1,%2,%3};"
        : "+f"(c[0]), "+f"(c[1]), "+f"(c[2]), "+f"(c[3])
        : "r"(a[0]), "r"(a[1]), "r"(a[2]), "r"(a[3]), "r"(b[0]), "r"(b[1]));
}

// ======================= bf16 split (x = hi + lo) ===========================
__global__ __launch_bounds__(256)
void split_bf16(const float* __restrict__ in, __nv_bfloat16* __restrict__ hi,
                __nv_bfloat16* __restrict__ lo, int n4)
{
    int i = blockIdx.x * 256 + threadIdx.x;
    if (i >= n4) return;
    float4 v = ((const float4*)in)[i];
    __nv_bfloat16 h0 = __float2bfloat16(v.x), h1 = __float2bfloat16(v.y);
    __nv_bfloat16 h2 = __float2bfloat16(v.z), h3 = __float2bfloat16(v.w);
    __nv_bfloat16 l0 = __float2bfloat16(v.x - __bfloat162float(h0));
    __nv_bfloat16 l1 = __float2bfloat16(v.y - __bfloat162float(h1));
    __nv_bfloat16 l2 = __float2bfloat16(v.z - __bfloat162float(h2));
    __nv_bfloat16 l3 = __float2bfloat16(v.w - __bfloat162float(h3));
    __nv_bfloat162 p;
    p.x = h0; p.y = h1; ((__nv_bfloat162*)hi)[i * 2]     = p;
    p.x = h2; p.y = h3; ((__nv_bfloat162*)hi)[i * 2 + 1] = p;
    p.x = l0; p.y = l1; ((__nv_bfloat162*)lo)[i * 2]     = p;
    p.x = l2; p.y = l3; ((__nv_bfloat162*)lo)[i * 2 + 1] = p;
}

// ======================= split-bf16 mma.sync GEMM ===========================
// C[M,N](fp32) = Ahi*Bhi^T + Ahi*Blo^T + Alo*Bhi^T (+bias), K=768.
// 128x128 CTA tile, BK=32, 8 warps (2x4), warp tile 64x32, cp.async 2-stage.
// smem tile: 128 rows x 40 halves (pad 32->40 for conflict-free ldmatrix).
#define TILE_PB  10240                  // 128*40*2 bytes
#define STAGE_B  (4 * TILE_PB)          // Ahi,Alo,Bhi,Blo
#define GEMM_SMEM (2 * STAGE_B)         // 81920

template <bool BIAS>
__global__ __launch_bounds__(256)
void gemm_mma(const __nv_bfloat16* __restrict__ Ahi, const __nv_bfloat16* __restrict__ Alo,
              const __nv_bfloat16* __restrict__ Bhi, const __nv_bfloat16* __restrict__ Blo,
              const float* __restrict__ bias, float* __restrict__ C, int ldC)
{
    extern __shared__ char smem[];
    const u32 base = smem_to_u32(smem);

    const int tid  = threadIdx.x;
    const int wid  = tid >> 5, lane = tid & 31;
    const int wm   = wid >> 2, wn = wid & 3;        // 2 x 4 warp grid
    const int n0   = blockIdx.x * 128, m0 = blockIdx.y * 128;

    // ldmatrix per-thread row/col offsets
    const int jA = lane >> 3, iA = lane & 7;
    const int mA = iA + (jA & 1) * 8;               // A: matrices (m,klo),(m+8,klo),(m,khi),(m+8,khi)
    const int kA = (jA >> 1) * 8;
    const int nB = iA + (lane >> 4) * 8;            // B: (n0-7,klo),(n0-7,khi),(n8-15,klo),(n8-15,khi)
    const int kB = (jA & 1) * 8;

    const __nv_bfloat16* s0 = Ahi + (size_t)m0 * 768;
    const __nv_bfloat16* s1 = Alo + (size_t)m0 * 768;
    const __nv_bfloat16* s2 = Bhi + (size_t)n0 * 768;
    const __nv_bfloat16* s3 = Blo + (size_t)n0 * 768;

    float acc[4][4][4];
#pragma unroll
    for (int mi = 0; mi < 4; ++mi)
#pragma unroll
        for (int ni = 0; ni < 4; ++ni)
#pragma unroll
            for (int k = 0; k < 4; ++k) acc[mi][ni][k] = 0.f;

    // ---- stage loader: 2048 16B-chunks / 256 thr = 8 per thread ----
    // id = tid + it*256 -> tile = it>>1 (static), idx = tid + (it&1)*256
#define LOAD_STAGE(stg, k0) do {                                              \
        u32 sb_ = base + (stg) * STAGE_B;                                     \
        _Pragma("unroll")                                                     \
        for (int it = 0; it < 8; ++it) {                                      \
            const __nv_bfloat16* src =                                        \
                (it >> 1) == 0 ? s0 : (it >> 1) == 1 ? s1                     \
              : (it >> 1) == 2 ? s2 : s3;                                     \
            int idx = tid + (it & 1) * 256;                                   \
            int r = idx >> 2, q = idx & 3;                                    \
            cp16(sb_ + (it >> 1) * TILE_PB + r * 80 + q * 16,                 \
                 src + (size_t)r * 768 + (k0) + q * 8);                       \
        }                                                                     \
    } while (0)

    LOAD_STAGE(0, 0);
    CP_COMMIT();

    for (int itk = 0; itk < 24; ++itk) {
        if (itk + 1 < 24) { LOAD_STAGE((itk + 1) & 1, (itk + 1) * 32); CP_COMMIT(); }
        if (itk + 1 < 24) cp_wait<1>(); else cp_wait<0>();
        __syncthreads();

        const u32 sb  = base + (itk & 1) * STAGE_B;
        const u32 aHi = sb, aLo = sb + TILE_PB;
        const u32 bHi = sb + 2 * TILE_PB, bLo = sb + 3 * TILE_PB;

#pragma unroll
        for (int ks = 0; ks < 2; ++ks) {
            u32 ah[4][4], al[4][4], bh[2][4], bl[2][4];
#pragma unroll
            for (int mi = 0; mi < 4; ++mi) {
                u32 ro = (u32)((wm * 64 + mi * 16 + mA) * 80 + (ks * 16 + kA) * 2);
                ldsm4(ah[mi], aHi + ro);
                ldsm4(al[mi], aLo + ro);
            }
#pragma unroll
            for (int p = 0; p < 2; ++p) {
                u32 ro = (u32)((wn * 32 + p * 16 + nB) * 80 + (ks * 16 + kB) * 2);
                ldsm4(bh[p], bHi + ro);
                ldsm4(bl[p], bLo + ro);
            }
#pragma unroll
            for (int mi = 0; mi < 4; ++mi)
#pragma unroll
                for (int ni = 0; ni < 4; ++ni) {
                    const u32* BH = &bh[ni >> 1][(ni & 1) * 2];
                    const u32* BL = &bl[ni >> 1][(ni & 1) * 2];
                    mma_bf16(acc[mi][ni], ah[mi], BH);
                    mma_bf16(acc[mi][ni], ah[mi], BL);
                    mma_bf16(acc[mi][ni], al[mi], BH);
                }
        }
        __syncthreads();
    }

    // ---- epilogue ----
    const int mrow = wm * 64 + (lane >> 2);
    const int ncol = wn * 32 + (lane & 3) * 2;
#pragma unroll
    for (int mi = 0; mi < 4; ++mi) {
#pragma unroll
        for (int ni = 0; ni < 4; ++ni) {
            int col = n0 + ncol + ni * 8;
            size_t r0 = (size_t)(m0 + mrow + mi * 16) * ldC + col;
            size_t r1 = r0 + 8 * (size_t)ldC;
            float2 v0, v1;
            v0.x = acc[mi][ni][0]; v0.y = acc[mi][ni][1];
            v1.x = acc[mi][ni][2]; v1.y = acc[mi][ni][3];
            if (BIAS) {
                float b0 = bias[col], b1 = bias[col + 1];
                v0.x += b0; v0.y += b1; v1.x += b0; v1.y += b1;
            }
            *(float2*)(C + r0) = v0;
            *(float2*)(C + r1) = v1;
        }
    }
#undef LOAD_STAGE
}

// ---------------- BN stats: deterministic two-stage column reduction -------
__global__ __launch_bounds__(256)
void bn_stats(const float* __restrict__ qkv)
{
    int c  = blockIdx.x * 256 + threadIdx.x;
    int r0 = blockIdx.y * 256;
    float s = 0.f, q = 0.f;
    for (int i = 0; i < 256; ++i) {
        float v = qkv[(size_t)(r0 + i) * C3 + c];
        s += v; q += v * v;
    }
    g_psum[blockIdx.y * C3 + c] = s;
    g_psq [blockIdx.y * C3 + c] = q;
}

__global__ __launch_bounds__(256)
void bn_finalize(const float* __restrict__ gamma, const float* __restrict__ beta)
{
    int c = blockIdx.x * 256 + threadIdx.x;
    float s = 0.f, q = 0.f;
    for (int i = 0; i < 32; ++i) { s += g_psum[i * C3 + c]; q += g_psq[i * C3 + c]; }
    float mean = s * (1.f / M_);
    float var  = q * (1.f / M_) - mean * mean;
    float rs   = rsqrtf(var + 1e-5f);
    float sc   = gamma[c] * rs;
    g_scale[c] = sc;
    g_shift[c] = beta[c] - mean * sc;
}

// ---------------- fused BN-apply + multistep LIF + bit-pack ----------------
__global__ __launch_bounds__(256)
void bnlif(const float* __restrict__ qkv)
{
    int gid   = blockIdx.x * 256 + threadIdx.x;
    int n     = gid & 1023;
    int t     = gid >> 10;
    int h     = t % H_;
    int which = t / H_;
    int c0    = which * C_ + h * D_;

    u64 bits[B_];
#pragma unroll
    for (int b = 0; b < B_; ++b) bits[b] = 0ull;

#pragma unroll
    for (int dq = 0; dq < 4; ++dq) {
        int cb = c0 + dq * 16;
        float sc[16], sh[16];
#pragma unroll
        for (int q4 = 0; q4 < 4; ++q4) {
            *(float4*)(sc + q4 * 4) = *(const float4*)(g_scale + cb + q4 * 4);
            *(float4*)(sh + q4 * 4) = *(const float4*)(g_shift + cb + q4 * 4);
        }
        float v[16];
#pragma unroll
        for (int d = 0; d < 16; ++d) v[d] = 0.f;

#pragma unroll
        for (int b = 0; b < B_; ++b) {
            const float* row = qkv + (size_t)(b * N_ + n) * C3 + cb;
            float xv[16];
#pragma unroll
            for (int q4 = 0; q4 < 4; ++q4)
                *(float4*)(xv + q4 * 4) = *(const float4*)(row + q4 * 4);
#pragma unroll
            for (int d = 0; d < 16; ++d) {
                float y = fmaf(xv[d], sc[d], sh[d]);
                v[d] = 0.5f * (v[d] + y);
                if (v[d] >= 1.0f) {
                    bits[b] |= 1ull << (dq * 16 + d);
                    v[d] = 0.f;
                }
            }
        }
    }
#pragma unroll
    for (int b = 0; b < B_; ++b)
        g_sbits[((size_t)(which * B_ + b) * H_ + h) * N_ + n] = bits[b];
}

// ---------------- attention: popcount QK + table-exp + fp32 PV GEMM --------
#define OFF_ET   0
#define OFF_VS   (OFF_ET + 128 * 128 * 4)
#define OFF_SKB  (OFF_VS + 128 * 64 * 4)
#define OFF_SVB  (OFF_SKB + 1024 * 8)
#define OFF_SQB  (OFF_SVB + 1024 * 8)
#define OFF_TAB  (OFF_SQB + 128 * 8)
#define OFF_DEN  (OFF_TAB + 272)
#define ATTN_SMEM (OFF_DEN + 256 * 4)

__global__ __launch_bounds__(256)
void attn_kernel(__nv_bfloat16* __restrict__ ohi, __nv_bfloat16* __restrict__ olo)
{
    extern __shared__ char smem[];
    float* Et   = (float*)(smem + OFF_ET);
    float* Vs   = (float*)(smem + OFF_VS);
    u64*   skb  = (u64*)  (smem + OFF_SKB);
    u64*   svb  = (u64*)  (smem + OFF_SVB);
    u64*   sqb  = (u64*)  (smem + OFF_SQB);
    float* tab  = (float*)(smem + OFF_TAB);
    float* den2 = (float*)(smem + OFF_DEN);

    const int tid = threadIdx.x;
    const int bh  = blockIdx.x;
    const int rt  = blockIdx.y;
    const int b   = bh / H_, h = bh % H_;

    const u64* qb = g_sbits + ((size_t)(0 * B_ + b) * H_ + h) * N_;
    const u64* kb = g_sbits + ((size_t)(1 * B_ + b) * H_ + h) * N_;
    const u64* vb = g_sbits + ((size_t)(2 * B_ + b) * H_ + h) * N_;

    for (int i = tid; i < N_; i += 256) { skb[i] = kb[i]; svb[i] = vb[i]; }
    if (tid < 128) sqb[tid] = qb[rt * 128 + tid];
    if (tid < 65)  tab[tid] = expf(0.125f * (float)tid);
    __syncthreads();

    const int r = tid >> 1, half = tid & 1;
    const u64 qr = sqb[r];
    const int ty = tid >> 4, tx = tid & 15;

    float acc[8][4];
#pragma unroll
    for (int i = 0; i < 8; ++i)
#pragma unroll
        for (int k = 0; k < 4; ++k) acc[i][k] = 0.f;
    float den_local = 0.f;

    for (int jt = 0; jt < 8; ++jt) {
        const u64* kt = skb + jt * 128 + half * 64;
#pragma unroll 4
        for (int jj = 0; jj < 64; ++jj) {
            int s = __popcll(qr & kt[jj]);
            float e = tab[s];
            Et[(half * 64 + jj) * 128 + r] = e;
            den_local += e;
        }
        for (int idx = tid; idx < 128 * 64; idx += 256) {
            int j = idx >> 6, d = idx & 63;
            Vs[idx] = (float)((svb[jt * 128 + j] >> d) & 1ull);
        }
        __syncthreads();
#pragma unroll 2
        for (int j = 0; j < 128; ++j) {
            float a[8], bb[4];
            *(float4*)(a)     = *(const float4*)&Et[j * 128 + ty * 8];
            *(float4*)(a + 4) = *(const float4*)&Et[j * 128 + ty * 8 + 4];
            *(float4*)(bb)    = *(const float4*)&Vs[j * 64 + tx * 4];
#pragma unroll
            for (int i = 0; i < 8; ++i)
#pragma unroll
                for (int k = 0; k < 4; ++k)
                    acc[i][k] = fmaf(a[i], bb[k], acc[i][k]);
        }
        __syncthreads();
    }

    den2[tid] = den_local;
    __syncthreads();

#pragma unroll
    for (int i = 0; i < 8; ++i) {
        int row = ty * 8 + i;
        float inv = 1.f / (den2[row * 2] + den2[row * 2 + 1]);
        size_t o = ((size_t)(b * N_) + rt * 128 + row) * C_ + h * D_ + tx * 4;
        float v0 = acc[i][0] * inv, v1 = acc[i][1] * inv;
        float v2 = acc[i][2] * inv, v3 = acc[i][3] * inv;
        __nv_bfloat16 h0 = __float2bfloat16(v0), h1 = __float2bfloat16(v1);
        __nv_bfloat16 h2 = __float2bfloat16(v2), h3 = __float2bfloat16(v3);
        __nv_bfloat162 p;
        p.x = h0; p.y = h1; *(__nv_bfloat162*)(ohi + o)     = p;
        p.x = h2; p.y = h3; *(__nv_bfloat162*)(ohi + o + 2) = p;
        p.x = __float2bfloat16(v0 - __bfloat162float(h0));
        p.y = __float2bfloat16(v1 - __bfloat162float(h1));
        *(__nv_bfloat162*)(olo + o) = p;
        p.x = __float2bfloat16(v2 - __bfloat162float(h2));
        p.y = __float2bfloat16(v3 - __bfloat162float(h3));
        *(__nv_bfloat162*)(olo + o + 2) = p;
    }
}

// ---------------- launch ----------------------------------------------------
extern "C" void kernel_launch(void* const* d_in, const int* in_sizes, int n_in,
                              void* d_out, int out_size)
{
    const float* x      = (const float*)d_in[0];
    const float* w_qkv  = (const float*)d_in[1];
    const float* gamma  = (const float*)d_in[2];
    const float* beta   = (const float*)d_in[3];
    const float* w_proj = (const float*)d_in[4];
    const float* b_proj = (const float*)d_in[5];
    float* out = (float*)d_out;

    float *qkv = nullptr;
    __nv_bfloat16 *xhi, *xlo, *w1hi, *w1lo, *ahi, *alo, *w2hi, *w2lo;
    cudaGetSymbolAddress((void**)&qkv,  g_qkv);
    cudaGetSymbolAddress((void**)&xhi,  g_xhi);
    cudaGetSymbolAddress((void**)&xlo,  g_xlo);
    cudaGetSymbolAddress((void**)&w1hi, g_w1hi);
    cudaGetSymbolAddress((void**)&w1lo, g_w1lo);
    cudaGetSymbolAddress((void**)&ahi,  g_ahi);
    cudaGetSymbolAddress((void**)&alo,  g_alo);
    cudaGetSymbolAddress((void**)&w2hi, g_w2hi);
    cudaGetSymbolAddress((void**)&w2lo, g_w2lo);

    cudaFuncSetAttribute(attn_kernel,
                         cudaFuncAttributeMaxDynamicSharedMemorySize, ATTN_SMEM);
    cudaFuncSetAttribute(gemm_mma<false>,
                         cudaFuncAttributeMaxDynamicSharedMemorySize, GEMM_SMEM);
    cudaFuncSetAttribute(gemm_mma<true>,
                         cudaFuncAttributeMaxDynamicSharedMemorySize, GEMM_SMEM);

    // 0) bf16 splits of x, w_qkv, w_proj
    split_bf16<<<(M_ * C_ / 4 + 255) / 256, 256>>>(x, xhi, xlo, M_ * C_ / 4);
    split_bf16<<<(C3 * C_ / 4 + 255) / 256, 256>>>(w_qkv, w1hi, w1lo, C3 * C_ / 4);
    split_bf16<<<(C_ * C_ / 4 + 255) / 256, 256>>>(w_proj, w2hi, w2lo, C_ * C_ / 4);
    // 1) qkv = x @ w_qkv^T (mma.sync split-bf16)
    gemm_mma<false><<<dim3(C3 / 128, M_ / 128), 256, GEMM_SMEM>>>(
        xhi, xlo, w1hi, w1lo, nullptr, qkv, C3);
    // 2) BN stats
    bn_stats<<<dim3(9, 32), 256>>>(qkv);
    bn_finalize<<<9, 256>>>(gamma, beta);
    // 3) BN apply + LIF + bit-pack
    bnlif<<<144, 256>>>(qkv);
    // 4) spiking attention -> bf16 split output
    attn_kernel<<<dim3(B_ * H_, 8), 256, ATTN_SMEM>>>(ahi, alo);
    // 5) out = attn @ w_proj^T + b_proj (mma.sync split-bf16)
    gemm_mma<true><<<dim3(C_ / 128, M_ / 128), 256, GEMM_SMEM>>>(
        ahi, alo, w2hi, w2lo, b_proj, out, C_);
}

// round 6
// speedup vs baseline: 2.3381x; 1.4881x over previous
#include <cuda_runtime.h>
#include <cuda_fp16.h>
#include <cstdint>
#include <cstddef>

typedef unsigned long long u64;
typedef unsigned int u32;

#define B_  8
#define N_  1024
#define C_  768
#define H_  12
#define D_  64
#define C3  2304
#define M_  8192   // B_*N_

// ---------------- scratch (device globals; no runtime allocation) ----------
__device__ float g_qkv [(size_t)M_ * C3];   // [8192, 2304] fp32
__device__ u64   g_sbits[3 * B_ * H_ * N_]; // [which][b][h][n] packed spikes
__device__ float g_psum[32 * C3];
__device__ float g_psq [32 * C3];
__device__ float g_scale[C3];
__device__ float g_shift[C3];
// fp16 split operands
__device__ __half g_xhi [(size_t)M_ * C_];
__device__ __half g_xlo [(size_t)M_ * C_];
__device__ __half g_w1hi[(size_t)C3 * C_];
__device__ __half g_w1lo[(size_t)C3 * C_];
__device__ __half g_ahi [(size_t)M_ * C_];   // attention out split
__device__ __half g_alo [(size_t)M_ * C_];
__device__ __half g_w2hi[(size_t)C_ * C_];
__device__ __half g_w2lo[(size_t)C_ * C_];

// ======================= baseline-PTX helpers ===============================
__device__ __forceinline__ u32 smem_to_u32(const void* p) {
    u32 a;
    asm("{ .reg .u64 t; cvta.to.shared.u64 t, %1; cvt.u32.u64 %0, t; }"
        : "=r"(a) : "l"(p));
    return a;
}
__device__ __forceinline__ void cp16(u32 dst, const void* src) {
    asm volatile("cp.async.cg.shared.global [%0], [%1], 16;"
                 :: "r"(dst), "l"(src));
}
#define CP_COMMIT() asm volatile("cp.async.commit_group;" ::: "memory")
template <int NN> __device__ __forceinline__ void cp_wait() {
    asm volatile("cp.async.wait_group %0;" :: "n"(NN) : "memory");
}
__device__ __forceinline__ void ldsm4(u32* r, u32 addr) {
    asm volatile("ldmatrix.sync.aligned.m8n8.x4.shared.b16 {%0,%1,%2,%3}, [%4];"
                 : "=r"(r[0]), "=r"(r[1]), "=r"(r[2]), "=r"(r[3]) : "r"(addr));
}
__device__ __forceinline__ void mma_f16(float* c, const u32* a, const u32* b) {
    asm volatile(
        "mma.sync.aligned.m16n8k16.row.col.f32.f16.f16.f32 "
        "{%0,%1,%2,%3}, {%4,%5,%6,%7}, {%8,%9}, {%0,%1,%2,%3};"
        : "+f"(c[0]), "+f"(c[1]), "+f"(c[2]), "+f"(c[3])
        : "r"(a[0]), "r"(a[1]), "r"(a[2]), "r"(a[3]), "r"(b[0]), "r"(b[1]));
}

// ======================= fp16 split (x = hi + lo) ===========================
__global__ __launch_bounds__(256)
void split_f16(const float* __restrict__ in, __half* __restrict__ hi,
               __half* __restrict__ lo, int n4)
{
    int i = blockIdx.x * 256 + threadIdx.x;
    if (i >= n4) return;
    float4 v = ((const float4*)in)[i];
    __half h0 = __float2half_rn(v.x), h1 = __float2half_rn(v.y);
    __half h2 = __float2half_rn(v.z), h3 = __float2half_rn(v.w);
    __half l0 = __float2half_rn(v.x - __half2float(h0));
    __half l1 = __float2half_rn(v.y - __half2float(h1));
    __half l2 = __float2half_rn(v.z - __half2float(h2));
    __half l3 = __float2half_rn(v.w - __half2float(h3));
    __half2 p;
    p.x = h0; p.y = h1; ((__half2*)hi)[i * 2]     = p;
    p.x = h2; p.y = h3; ((__half2*)hi)[i * 2 + 1] = p;
    p.x = l0; p.y = l1; ((__half2*)lo)[i * 2]     = p;
    p.x = l2; p.y = l3; ((__half2*)lo)[i * 2 + 1] = p;
}

// ======================= split-fp16 mma.sync GEMM ===========================
// C[M,N](fp32) = Ahi*Bhi^T + Ahi*Blo^T + Alo*Bhi^T (+bias), K=768.
// 128x128 CTA tile, BK=32, 8 warps (2x4), warp tile 64x32, cp.async 2-stage.
#define TILE_PB  10240                  // 128*40*2 bytes
#define STAGE_B  (4 * TILE_PB)          // Ahi,Alo,Bhi,Blo
#define GEMM_SMEM (2 * STAGE_B)         // 81920

template <bool BIAS>
__global__ __launch_bounds__(256)
void gemm_mma(const __half* __restrict__ Ahi, const __half* __restrict__ Alo,
              const __half* __restrict__ Bhi, const __half* __restrict__ Blo,
              const float* __restrict__ bias, float* __restrict__ C, int ldC)
{
    extern __shared__ char smem[];
    const u32 base = smem_to_u32(smem);

    const int tid  = threadIdx.x;
    const int wid  = tid >> 5, lane = tid & 31;
    const int wm   = wid >> 2, wn = wid & 3;
    const int n0   = blockIdx.x * 128, m0 = blockIdx.y * 128;

    const int jA = lane >> 3, iA = lane & 7;
    const int mA = iA + (jA & 1) * 8;
    const int kA = (jA >> 1) * 8;
    const int nB = iA + (lane >> 4) * 8;
    const int kB = (jA & 1) * 8;

    const __half* s0 = Ahi + (size_t)m0 * 768;
    const __half* s1 = Alo + (size_t)m0 * 768;
    const __half* s2 = Bhi + (size_t)n0 * 768;
    const __half* s3 = Blo + (size_t)n0 * 768;

    float acc[4][4][4];
#pragma unroll
    for (int mi = 0; mi < 4; ++mi)
#pragma unroll
        for (int ni = 0; ni < 4; ++ni)
#pragma unroll
            for (int k = 0; k < 4; ++k) acc[mi][ni][k] = 0.f;

#define LOAD_STAGE(stg, k0) do {                                              \
        u32 sb_ = base + (stg) * STAGE_B;                                     \
        _Pragma("unroll")                                                     \
        for (int it = 0; it < 8; ++it) {                                      \
            const __half* src =                                               \
                (it >> 1) == 0 ? s0 : (it >> 1) == 1 ? s1                     \
              : (it >> 1) == 2 ? s2 : s3;                                     \
            int idx = tid + (it & 1) * 256;                                   \
            int r = idx >> 2, q = idx & 3;                                    \
            cp16(sb_ + (it >> 1) * TILE_PB + r * 80 + q * 16,                 \
                 src + (size_t)r * 768 + (k0) + q * 8);                       \
        }                                                                     \
    } while (0)

    LOAD_STAGE(0, 0);
    CP_COMMIT();

    for (int itk = 0; itk < 24; ++itk) {
        if (itk + 1 < 24) { LOAD_STAGE((itk + 1) & 1, (itk + 1) * 32); CP_COMMIT(); }
        if (itk + 1 < 24) cp_wait<1>(); else cp_wait<0>();
        __syncthreads();

        const u32 sb  = base + (itk & 1) * STAGE_B;
        const u32 aHi = sb, aLo = sb + TILE_PB;
        const u32 bHi = sb + 2 * TILE_PB, bLo = sb + 3 * TILE_PB;

#pragma unroll
        for (int ks = 0; ks < 2; ++ks) {
            u32 ah[4][4], al[4][4], bh[2][4], bl[2][4];
#pragma unroll
            for (int mi = 0; mi < 4; ++mi) {
                u32 ro = (u32)((wm * 64 + mi * 16 + mA) * 80 + (ks * 16 + kA) * 2);
                ldsm4(ah[mi], aHi + ro);
                ldsm4(al[mi], aLo + ro);
            }
#pragma unroll
            for (int p = 0; p < 2; ++p) {
                u32 ro = (u32)((wn * 32 + p * 16 + nB) * 80 + (ks * 16 + kB) * 2);
                ldsm4(bh[p], bHi + ro);
                ldsm4(bl[p], bLo + ro);
            }
#pragma unroll
            for (int mi = 0; mi < 4; ++mi)
#pragma unroll
                for (int ni = 0; ni < 4; ++ni) {
                    const u32* BH = &bh[ni >> 1][(ni & 1) * 2];
                    const u32* BL = &bl[ni >> 1][(ni & 1) * 2];
                    mma_f16(acc[mi][ni], ah[mi], BH);
                    mma_f16(acc[mi][ni], ah[mi], BL);
                    mma_f16(acc[mi][ni], al[mi], BH);
                }
        }
        __syncthreads();
    }

    const int mrow = wm * 64 + (lane >> 2);
    const int ncol = wn * 32 + (lane & 3) * 2;
#pragma unroll
    for (int mi = 0; mi < 4; ++mi) {
#pragma unroll
        for (int ni = 0; ni < 4; ++ni) {
            int col = n0 + ncol + ni * 8;
            size_t r0 = (size_t)(m0 + mrow + mi * 16) * ldC + col;
            size_t r1 = r0 + 8 * (size_t)ldC;
            float2 v0, v1;
            v0.x = acc[mi][ni][0]; v0.y = acc[mi][ni][1];
            v1.x = acc[mi][ni][2]; v1.y = acc[mi][ni][3];
            if (BIAS) {
                float b0 = bias[col], b1 = bias[col + 1];
                v0.x += b0; v0.y += b1; v1.x += b0; v1.y += b1;
            }
            *(float2*)(C + r0) = v0;
            *(float2*)(C + r1) = v1;
        }
    }
#undef LOAD_STAGE
}

// ---------------- BN stats: deterministic two-stage column reduction -------
__global__ __launch_bounds__(256)
void bn_stats(const float* __restrict__ qkv)
{
    int c  = blockIdx.x * 256 + threadIdx.x;
    int r0 = blockIdx.y * 256;
    float s = 0.f, q = 0.f;
    for (int i = 0; i < 256; ++i) {
        float v = qkv[(size_t)(r0 + i) * C3 + c];
        s += v; q += v * v;
    }
    g_psum[blockIdx.y * C3 + c] = s;
    g_psq [blockIdx.y * C3 + c] = q;
}

__global__ __launch_bounds__(256)
void bn_finalize(const float* __restrict__ gamma, const float* __restrict__ beta)
{
    int c = blockIdx.x * 256 + threadIdx.x;
    float s = 0.f, q = 0.f;
    for (int i = 0; i < 32; ++i) { s += g_psum[i * C3 + c]; q += g_psq[i * C3 + c]; }
    float mean = s * (1.f / M_);
    float var  = q * (1.f / M_) - mean * mean;
    float rs   = rsqrtf(var + 1e-5f);
    float sc   = gamma[c] * rs;
    g_scale[c] = sc;
    g_shift[c] = beta[c] - mean * sc;
}

// ---------------- fused BN-apply + multistep LIF + bit-pack ----------------
__global__ __launch_bounds__(256)
void bnlif(const float* __restrict__ qkv)
{
    int gid   = blockIdx.x * 256 + threadIdx.x;
    int n     = gid & 1023;
    int t     = gid >> 10;
    int h     = t % H_;
    int which = t / H_;
    int c0    = which * C_ + h * D_;

    u64 bits[B_];
#pragma unroll
    for (int b = 0; b < B_; ++b) bits[b] = 0ull;

#pragma unroll
    for (int dq = 0; dq < 4; ++dq) {
        int cb = c0 + dq * 16;
        float sc[16], sh[16];
#pragma unroll
        for (int q4 = 0; q4 < 4; ++q4) {
            *(float4*)(sc + q4 * 4) = *(const float4*)(g_scale + cb + q4 * 4);
            *(float4*)(sh + q4 * 4) = *(const float4*)(g_shift + cb + q4 * 4);
        }
        float v[16];
#pragma unroll
        for (int d = 0; d < 16; ++d) v[d] = 0.f;

#pragma unroll
        for (int b = 0; b < B_; ++b) {
            const float* row = qkv + (size_t)(b * N_ + n) * C3 + cb;
            float xv[16];
#pragma unroll
            for (int q4 = 0; q4 < 4; ++q4)
                *(float4*)(xv + q4 * 4) = *(const float4*)(row + q4 * 4);
#pragma unroll
            for (int d = 0; d < 16; ++d) {
                float y = fmaf(xv[d], sc[d], sh[d]);
                v[d] = 0.5f * (v[d] + y);
                if (v[d] >= 1.0f) {
                    bits[b] |= 1ull << (dq * 16 + d);
                    v[d] = 0.f;
                }
            }
        }
    }
#pragma unroll
    for (int b = 0; b < B_; ++b)
        g_sbits[((size_t)(which * B_ + b) * H_ + h) * N_ + n] = bits[b];
}

// ============== attention v2: full tensor-core (QK mma, exp, PV mma) ========
// block = (bh, row-tile of 128). 8 warps.
// QK: S[128,128] = Q[128,64] K^T, fp16 0/1 exact -> integer scores.
// e = exp2(s*log2e/8); split fp16 hi/lo -> E tiles.
// PV: out[128,80] += E[128,128] x Vaug[128,80]; Vaug col64 = 1 -> denominator.
#define A2_Q    0                       // 128 x 72 halves  (18432 B)
#define A2_K    18432                   // 128 x 72 halves
#define A2_VT   36864                   // 96 rows(n) x 136 cols(k) halves (26112 B)
#define A2_EH   62976                   // 128 x 136 halves (34816 B)
#define A2_EL   97792                   // 128 x 136 halves
#define A2_DEN  132608                  // 128 floats
#define ATTN2_SMEM 133120

__global__ __launch_bounds__(256)
void attn2(__half* __restrict__ ohi, __half* __restrict__ olo)
{
    extern __shared__ char sm[];
    const u32 base = smem_to_u32(sm);
    const int tid = threadIdx.x, lane = tid & 31, wid = tid >> 5;
    const int bh = blockIdx.x, rt = blockIdx.y;
    const int b = bh / H_, h = bh % H_;

    const u64* qb = g_sbits + ((size_t)(0 * B_ + b) * H_ + h) * N_ + rt * 128;
    const u64* kb = g_sbits + ((size_t)(1 * B_ + b) * H_ + h) * N_;
    const u64* vb = g_sbits + ((size_t)(2 * B_ + b) * H_ + h) * N_;

    __half* sQ  = (__half*)(sm + A2_Q);
    __half* sK  = (__half*)(sm + A2_K);
    __half* sVt = (__half*)(sm + A2_VT);
    __half* sEh = (__half*)(sm + A2_EH);
    __half* sEl = (__half*)(sm + A2_EL);
    float*  den = (float*)(sm + A2_DEN);

    const int iA = lane & 7, jA = lane >> 3;
    const int mA = iA + (jA & 1) * 8;
    const int kA = (jA >> 1) * 8;
    const int nB = iA + (lane >> 4) * 8;
    const int kB = (jA & 1) * 8;

    const int wmQ = wid >> 2, wnQ = wid & 3;   // QK: 2x4, warp tile 64x32
    const int wmP = wid >> 1, wnP = wid & 1;   // PV: 4x2, warp tile 32x40

    // convert Q once (128 x 64 -> fp16, row pad 72)
    {
        int j = tid >> 1, hs = tid & 1;
        u64 qr = qb[j] >> (hs * 32);
        __half* dst = sQ + j * 72 + hs * 32;
#pragma unroll
        for (int d = 0; d < 32; ++d)
            dst[d] = __float2half_rn((float)((qr >> d) & 1ull));
    }

    float oacc[2][5][4];
#pragma unroll
    for (int mi = 0; mi < 2; ++mi)
#pragma unroll
        for (int ni = 0; ni < 5; ++ni)
#pragma unroll
            for (int k = 0; k < 4; ++k) oacc[mi][ni][k] = 0.f;

    for (int jt = 0; jt < 8; ++jt) {
        // ---- convert K tile (128 x 64, pad 72) ----
        {
            int j = tid >> 1, hs = tid & 1;
            u64 kr = kb[jt * 128 + j] >> (hs * 32);
            __half* dst = sK + j * 72 + hs * 32;
#pragma unroll
            for (int d = 0; d < 32; ++d)
                dst[d] = __float2half_rn((float)((kr >> d) & 1ull));
        }
        // ---- convert Vaug transposed: sVt[d][j], 96 x 128 (pad 136) ----
#pragma unroll 4
        for (int it = 0; it < 48; ++it) {
            int idx = it * 256 + tid;
            int d = idx >> 7, j = idx & 127;
            float v = 0.f;
            if (d < 64) v = (float)((vb[jt * 128 + j] >> d) & 1ull);
            else if (d == 64) v = 1.f;
            sVt[d * 136 + j] = __float2half_rn(v);
        }
        __syncthreads();

        // ---- QK + exp + E store (split n in halves to cap registers) ----
#pragma unroll
        for (int nh = 0; nh < 2; ++nh) {
            float sacc[4][2][4];
#pragma unroll
            for (int mi = 0; mi < 4; ++mi)
#pragma unroll
                for (int nj = 0; nj < 2; ++nj)
#pragma unroll
                    for (int k = 0; k < 4; ++k) sacc[mi][nj][k] = 0.f;
#pragma unroll
            for (int ks = 0; ks < 4; ++ks) {
                u32 aq[4][4], bk[4];
#pragma unroll
                for (int mi = 0; mi < 4; ++mi)
                    ldsm4(aq[mi], base + A2_Q +
                          (u32)(((wmQ * 64 + mi * 16 + mA) * 72 + ks * 16 + kA) * 2));
                ldsm4(bk, base + A2_K +
                      (u32)(((wnQ * 32 + nh * 16 + nB) * 72 + ks * 16 + kB) * 2));
#pragma unroll
                for (int mi = 0; mi < 4; ++mi)
#pragma unroll
                    for (int nj = 0; nj < 2; ++nj)
                        mma_f16(sacc[mi][nj], aq[mi], &bk[nj * 2]);
            }
            const float CEXP = 0.18033688011f;   // log2(e)/8
#pragma unroll
            for (int mi = 0; mi < 4; ++mi)
#pragma unroll
                for (int nj = 0; nj < 2; ++nj) {
                    int r0 = wmQ * 64 + mi * 16 + (lane >> 2);
                    int c0 = wnQ * 32 + nh * 16 + nj * 8 + (lane & 3) * 2;
                    float e0 = exp2f(sacc[mi][nj][0] * CEXP);
                    float e1 = exp2f(sacc[mi][nj][1] * CEXP);
                    float e2 = exp2f(sacc[mi][nj][2] * CEXP);
                    float e3 = exp2f(sacc[mi][nj][3] * CEXP);
                    __half h0 = __float2half_rn(e0), h1 = __float2half_rn(e1);
                    __half h2 = __float2half_rn(e2), h3 = __float2half_rn(e3);
                    __half2 p;
                    p.x = h0; p.y = h1; *(__half2*)(sEh + r0 * 136 + c0) = p;
                    p.x = h2; p.y = h3; *(__half2*)(sEh + (r0 + 8) * 136 + c0) = p;
                    p.x = __float2half_rn(e0 - __half2float(h0));
                    p.y = __float2half_rn(e1 - __half2float(h1));
                    *(__half2*)(sEl + r0 * 136 + c0) = p;
                    p.x = __float2half_rn(e2 - __half2float(h2));
                    p.y = __float2half_rn(e3 - __half2float(h3));
                    *(__half2*)(sEl + (r0 + 8) * 136 + c0) = p;
                }
        }
        __syncthreads();

        // ---- PV: out += (Ehi + Elo) x Vaug ----
#pragma unroll
        for (int ks = 0; ks < 8; ++ks) {
            u32 aeh[2][4], ael[2][4], bv[3][4];
#pragma unroll
            for (int mi = 0; mi < 2; ++mi) {
                u32 ro = (u32)(((wmP * 32 + mi * 16 + mA) * 136 + ks * 16 + kA) * 2);
                ldsm4(aeh[mi], base + A2_EH + ro);
                ldsm4(ael[mi], base + A2_EL + ro);
            }
#pragma unroll
            for (int p = 0; p < 3; ++p)
                ldsm4(bv[p], base + A2_VT +
                      (u32)(((wnP * 40 + p * 16 + nB) * 136 + ks * 16 + kB) * 2));
#pragma unroll
            for (int mi = 0; mi < 2; ++mi)
#pragma unroll
                for (int ni = 0; ni < 5; ++ni) {
                    const u32* bb = (ni < 4) ? &bv[ni >> 1][(ni & 1) * 2] : &bv[2][0];
                    mma_f16(oacc[mi][ni], aeh[mi], bb);
                    mma_f16(oacc[mi][ni], ael[mi], bb);
                }
        }
        __syncthreads();
    }

    // ---- denominator (global col 64 = wnP1, ni3, lane&3==0) ----
    if (wnP == 1 && (lane & 3) == 0) {
#pragma unroll
        for (int mi = 0; mi < 2; ++mi) {
            int r0 = wmP * 32 + mi * 16 + (lane >> 2);
            den[r0]     = oacc[mi][3][0];
            den[r0 + 8] = oacc[mi][3][2];
        }
    }
    __syncthreads();

    // ---- normalize + write fp16 hi/lo split ----
    const int nlim = (wnP == 0) ? 5 : 3;
#pragma unroll
    for (int mi = 0; mi < 2; ++mi) {
        int r0 = wmP * 32 + mi * 16 + (lane >> 2);
        float i0 = 1.f / den[r0], i1 = 1.f / den[r0 + 8];
        size_t gr0 = ((size_t)(b * N_ + rt * 128 + r0)) * C_ + h * 64;
        size_t gr1 = gr0 + 8 * (size_t)C_;
#pragma unroll
        for (int ni = 0; ni < 5; ++ni) {
            if (ni >= nlim) break;
            int c0 = wnP * 40 + ni * 8 + (lane & 3) * 2;
            float v0 = oacc[mi][ni][0] * i0, v1 = oacc[mi][ni][1] * i0;
            float v2 = oacc[mi][ni][2] * i1, v3 = oacc[mi][ni][3] * i1;
            __half h0 = __float2half_rn(v0), h1 = __float2half_rn(v1);
            __half h2 = __float2half_rn(v2), h3 = __float2half_rn(v3);
            __half2 p;
            p.x = h0; p.y = h1; *(__half2*)(ohi + gr0 + c0) = p;
            p.x = h2; p.y = h3; *(__half2*)(ohi + gr1 + c0) = p;
            p.x = __float2half_rn(v0 - __half2float(h0));
            p.y = __float2half_rn(v1 - __half2float(h1));
            *(__half2*)(olo + gr0 + c0) = p;
            p.x = __float2half_rn(v2 - __half2float(h2));
            p.y = __float2half_rn(v3 - __half2float(h3));
            *(__half2*)(olo + gr1 + c0) = p;
        }
    }
}

// ---------------- launch ----------------------------------------------------
extern "C" void kernel_launch(void* const* d_in, const int* in_sizes, int n_in,
                              void* d_out, int out_size)
{
    const float* x      = (const float*)d_in[0];
    const float* w_qkv  = (const float*)d_in[1];
    const float* gamma  = (const float*)d_in[2];
    const float* beta   = (const float*)d_in[3];
    const float* w_proj = (const float*)d_in[4];
    const float* b_proj = (const float*)d_in[5];
    float* out = (float*)d_out;

    float *qkv = nullptr;
    __half *xhi, *xlo, *w1hi, *w1lo, *ahi, *alo, *w2hi, *w2lo;
    cudaGetSymbolAddress((void**)&qkv,  g_qkv);
    cudaGetSymbolAddress((void**)&xhi,  g_xhi);
    cudaGetSymbolAddress((void**)&xlo,  g_xlo);
    cudaGetSymbolAddress((void**)&w1hi, g_w1hi);
    cudaGetSymbolAddress((void**)&w1lo, g_w1lo);
    cudaGetSymbolAddress((void**)&ahi,  g_ahi);
    cudaGetSymbolAddress((void**)&alo,  g_alo);
    cudaGetSymbolAddress((void**)&w2hi, g_w2hi);
    cudaGetSymbolAddress((void**)&w2lo, g_w2lo);

    cudaFuncSetAttribute(attn2,
                         cudaFuncAttributeMaxDynamicSharedMemorySize, ATTN2_SMEM);
    cudaFuncSetAttribute(gemm_mma<false>,
                         cudaFuncAttributeMaxDynamicSharedMemorySize, GEMM_SMEM);
    cudaFuncSetAttribute(gemm_mma<true>,
                         cudaFuncAttributeMaxDynamicSharedMemorySize, GEMM_SMEM);

    // 0) fp16 splits of x, w_qkv, w_proj
    split_f16<<<(M_ * C_ / 4 + 255) / 256, 256>>>(x, xhi, xlo, M_ * C_ / 4);
    split_f16<<<(C3 * C_ / 4 + 255) / 256, 256>>>(w_qkv, w1hi, w1lo, C3 * C_ / 4);
    split_f16<<<(C_ * C_ / 4 + 255) / 256, 256>>>(w_proj, w2hi, w2lo, C_ * C_ / 4);
    // 1) qkv = x @ w_qkv^T (mma.sync split-fp16)
    gemm_mma<false><<<dim3(C3 / 128, M_ / 128), 256, GEMM_SMEM>>>(
        xhi, xlo, w1hi, w1lo, nullptr, qkv, C3);
    // 2) BN stats
    bn_stats<<<dim3(9, 32), 256>>>(qkv);
    bn_finalize<<<9, 256>>>(gamma, beta);
    // 3) BN apply + LIF + bit-pack
    bnlif<<<144, 256>>>(qkv);
    // 4) tensor-core spiking attention -> fp16 split output
    attn2<<<dim3(B_ * H_, 8), 256, ATTN2_SMEM>>>(ahi, alo);
    // 5) out = attn @ w_proj^T + b_proj (mma.sync split-fp16)
    gemm_mma<true><<<dim3(C_ / 128, M_ / 128), 256, GEMM_SMEM>>>(
        ahi, alo, w2hi, w2lo, b_proj, out, C_);
}